// round 6
// baseline (speedup 1.0000x reference)
#include <cuda_runtime.h>

#define B_    2048
#define FS_   32
#define FA_   16
#define T_    512
#define H_    64
#define SQRT_DT_ 0.22360679774997896f
#define MIN_V_  (-5.0f)
#define MAX_V_  (5.0f)

typedef unsigned long long u64;

__device__ __forceinline__ u64 pack2(float lo, float hi) {
    u64 r; asm("mov.b64 %0, {%1, %2};" : "=l"(r) : "f"(lo), "f"(hi)); return r;
}
__device__ __forceinline__ float2 unpack2(u64 v) {
    float2 f; asm("mov.b64 {%0, %1}, %2;" : "=f"(f.x), "=f"(f.y) : "l"(v)); return f;
}
// packed dual fp32 FMA (sm_100+)
__device__ __forceinline__ u64 ffma2(u64 a, u64 b, u64 c) {
    u64 d; asm("fma.rn.f32x2 %0, %1, %2, %3;" : "=l"(d) : "l"(a), "l"(b), "l"(c)); return d;
}
// accurate tanh from ex2.approx + rcp.approx (~1e-7 abs err)
__device__ __forceinline__ float tanh_acc(float x) {
    float e, r;
    asm("ex2.approx.f32 %0, %1;" : "=f"(e) : "f"(x * 2.8853900817779268f)); // 2*log2(e)
    asm("rcp.approx.f32 %0, %1;" : "=f"(r) : "f"(e + 1.0f));
    return (e - 1.0f) * r;
}

// Block = 128 threads = 4 warps = 2 (f,g) pairs. Each pair owns 8 batch
// elements split into two sets A/B of 4. Per step each warp pipelines:
// sync(S) -> finalize(S,t-1) -> compute(S,t) -> publish(S,t) across S=A,B,
// so a full phase of independent compute separates publish from consume and
// the per-set named barriers never block in steady state. Full weights stay
// register-resident (per-lane smem weights proved crossbar-bound in R5).
__global__ void __launch_bounds__(128, 1)
sde_kernel(const float* __restrict__ a_in,   // (B, FA, T)
           const float* __restrict__ x0,     // (B, FS)
           const float* __restrict__ noise,  // (T-1, B, FS)
           const float* __restrict__ Wf1, const float* __restrict__ bf1,
           const float* __restrict__ Wf2, const float* __restrict__ bf2,
           const float* __restrict__ Wg1, const float* __restrict__ bg1,
           const float* __restrict__ Wg2, const float* __restrict__ bg2,
           float* __restrict__ out)          // (B, FS, T)
{
    const int tid  = threadIdx.x;
    const int wid  = tid >> 5;
    const int lane = tid & 31;
    const int pair = wid >> 1;            // 0..1
    const bool is_g = (wid & 1) != 0;
    const int el0  = pair * 8;            // 8 elements per pair
    const int gb0  = blockIdx.x * 16 + el0;

    __shared__ __align__(16) float v_sm[4][8][64];            // per-warp x/h (8KB)
    __shared__ __align__(16) float a_sg[2][16][4][16];        // a tiles (8KB)
    __shared__ __align__(16) float ex_sm[2][2][2][2][4][32];  // [pair][S][tb][role][e][lane] (16KB)

    const float* W1 = is_g ? Wg1 : Wf1;
    const float* b1 = is_g ? bg1 : bf1;
    const float* W2 = is_g ? Wg2 : Wf2;
    const float* b2 = is_g ? bg2 : bf2;

    // -------- register-resident weights, packed (k, k+1) over k --------
    u64 w1a[24], w1b[24], w2p[32];
#pragma unroll
    for (int kp = 0; kp < 24; kp++) {
        w1a[kp] = pack2(W1[(2*kp)*H_ + lane],      W1[(2*kp+1)*H_ + lane]);
        w1b[kp] = pack2(W1[(2*kp)*H_ + lane + 32], W1[(2*kp+1)*H_ + lane + 32]);
    }
#pragma unroll
    for (int kp = 0; kp < 32; kp++) {
        w2p[kp] = pack2(W2[(2*kp)*FS_ + lane], W2[(2*kp+1)*FS_ + lane]);
    }
    const float bias1a = b1[lane];
    const float bias1b = b1[lane + 32];
    const float bias2  = b2[lane];

    const float* a_base = a_in + (size_t)gb0 * (FA_*T_) + (size_t)(lane >> 1) * T_ + (lane & 1) * 2;
    float*       out_b  = out  + (size_t)gb0 * (FS_*T_) + (size_t)lane * T_;

    float2 areg[8];          // f: prefetched a-tiles for 8 elements
    float  eps_cur[2][4];    // g: this-step noise per set

    // -------- prologue --------
#pragma unroll
    for (int e = 0; e < 8; e++) {
        float xv = x0[(size_t)(gb0 + e) * FS_ + lane];
        v_sm[wid][e][lane] = xv;
        if (!is_g) out_b[(size_t)e * (FS_*T_)] = xv;
    }
    if (!is_g) {
#pragma unroll
        for (int e = 0; e < 8; e++) {
            float2 v = *reinterpret_cast<const float2*>(a_base + (size_t)e * (FA_*T_));
            a_sg[0][el0 + e][(lane & 1)*2 + 0][lane >> 1] = v.x;
            a_sg[0][el0 + e][(lane & 1)*2 + 1][lane >> 1] = v.y;
        }
#pragma unroll
        for (int e = 0; e < 8; e++)
            areg[e] = *reinterpret_cast<const float2*>(a_base + (size_t)e * (FA_*T_) + 4);
    } else {
#pragma unroll
        for (int S = 0; S < 2; S++)
#pragma unroll
            for (int e = 0; e < 4; e++)
                eps_cur[S][e] = noise[(size_t)(gb0 + S*4 + e) * FS_ + lane];
    }
    __syncthreads();

#pragma unroll 1
    for (int t = 1; t < T_; t++) {
        const int ai  = t - 1;
        const int tb  = t & 1;
        const int ptb = tb ^ 1;
        const int g4  = ai >> 2;
        const int buf = g4 & 1;
        const int sl  = ai & 3;

#pragma unroll
        for (int S = 0; S < 2; S++) {
            const int bar_id = 1 + pair * 2 + S;
            const int eb = S * 4;             // element base within pair

            // ---- consume previous step's exchange (skipped at t==1) ----
            if (t > 1) {
                asm volatile("bar.sync %0, 64;" :: "r"(bar_id) : "memory");
#pragma unroll
                for (int e = 0; e < 4; e++) {
                    float xv = ex_sm[pair][S][ptb][0][e][lane]
                             + ex_sm[pair][S][ptb][1][e][lane];
                    xv = fminf(fmaxf(xv, MIN_V_), MAX_V_);
                    v_sm[wid][eb + e][lane] = xv;
                    if (!is_g) out_b[(size_t)(eb + e) * (FS_*T_) + (t - 1)] = xv;
                }
                __syncwarp();
            }

            // ---- compute(S, t) ----
            float eps_u[4];
            if (is_g) {
#pragma unroll
                for (int e = 0; e < 4; e++) eps_u[e] = eps_cur[S][e];
                if (t < T_ - 1) {
                    const float* np = noise + (size_t)t * (B_*FS_)
                                    + (size_t)(gb0 + eb) * FS_ + lane;
#pragma unroll
                    for (int e = 0; e < 4; e++) eps_cur[S][e] = np[e * FS_];
                }
            }

            // layer 1 (48 -> 64), 8 chains
            u64 aa[4], ab[4];
#pragma unroll
            for (int e = 0; e < 4; e++) { aa[e] = 0ull; ab[e] = 0ull; }
#pragma unroll
            for (int e = 0; e < 4; e++) {
                const ulonglong2* ap = reinterpret_cast<const ulonglong2*>(&a_sg[buf][el0+eb+e][sl][0]);
                const ulonglong2* xp = reinterpret_cast<const ulonglong2*>(&v_sm[wid][eb+e][0]);
#pragma unroll
                for (int q = 0; q < 4; q++) {            // s[0:16) = a_t
                    ulonglong2 v = ap[q];
                    aa[e] = ffma2(v.x, w1a[2*q],   aa[e]);
                    aa[e] = ffma2(v.y, w1a[2*q+1], aa[e]);
                    ab[e] = ffma2(v.x, w1b[2*q],   ab[e]);
                    ab[e] = ffma2(v.y, w1b[2*q+1], ab[e]);
                }
#pragma unroll
                for (int q = 0; q < 8; q++) {            // s[16:48) = x_t
                    ulonglong2 v = xp[q];
                    aa[e] = ffma2(v.x, w1a[8+2*q], aa[e]);
                    aa[e] = ffma2(v.y, w1a[9+2*q], aa[e]);
                    ab[e] = ffma2(v.x, w1b[8+2*q], ab[e]);
                    ab[e] = ffma2(v.y, w1b[9+2*q], ab[e]);
                }
            }
            // tanh + stash h (overwrites x in private buffer)
#pragma unroll
            for (int e = 0; e < 4; e++) {
                float2 u = unpack2(aa[e]);
                float2 v = unpack2(ab[e]);
                v_sm[wid][eb+e][lane]      = tanh_acc(u.x + u.y + bias1a);
                v_sm[wid][eb+e][lane + 32] = tanh_acc(v.x + v.y + bias1b);
            }
            __syncwarp();

            // layer 2 (64 -> 32), 8 chains
            float o[4];
#pragma unroll
            for (int e = 0; e < 4; e++) {
                const ulonglong2* hp = reinterpret_cast<const ulonglong2*>(&v_sm[wid][eb+e][0]);
                u64 c0 = 0ull, c1 = 0ull;
#pragma unroll
                for (int q = 0; q < 16; q++) {
                    ulonglong2 v = hp[q];
                    c0 = ffma2(v.x, w2p[2*q],   c0);
                    c1 = ffma2(v.y, w2p[2*q+1], c1);
                }
                float2 u0 = unpack2(c0), u1 = unpack2(c1);
                o[e] = (u0.x + u0.y) + (u1.x + u1.y) + bias2;
            }

            // publish: f -> o_f, g -> diffusion d
            if (!is_g) {
#pragma unroll
                for (int e = 0; e < 4; e++) ex_sm[pair][S][tb][0][e][lane] = o[e];
            } else {
#pragma unroll
                for (int e = 0; e < 4; e++)
                    ex_sm[pair][S][tb][1][e][lane] = o[e] * (eps_u[e] * SQRT_DT_);
            }

            // f: a-tile staging once per t (during phase A, fills slack)
            if (!is_g && S == 0) {
                if (sl == 2 && g4 + 1 < 128) {
#pragma unroll
                    for (int e = 0; e < 8; e++) {
                        a_sg[buf ^ 1][el0 + e][(lane & 1)*2 + 0][lane >> 1] = areg[e].x;
                        a_sg[buf ^ 1][el0 + e][(lane & 1)*2 + 1][lane >> 1] = areg[e].y;
                    }
                }
                if (sl == 3 && g4 + 2 < 128) {
                    const float* ap = a_base + (size_t)(g4 + 2) * 4;
#pragma unroll
                    for (int e = 0; e < 8; e++)
                        areg[e] = *reinterpret_cast<const float2*>(ap + (size_t)e * (FA_*T_));
                }
            }
        }
    }

    // -------- tail: finalize t = 511 for both sets --------
#pragma unroll
    for (int S = 0; S < 2; S++) {
        const int bar_id = 1 + pair * 2 + S;
        const int eb = S * 4;
        asm volatile("bar.sync %0, 64;" :: "r"(bar_id) : "memory");
        if (!is_g) {
#pragma unroll
            for (int e = 0; e < 4; e++) {
                float xv = ex_sm[pair][S][(T_-1) & 1][0][e][lane]
                         + ex_sm[pair][S][(T_-1) & 1][1][e][lane];
                xv = fminf(fmaxf(xv, MIN_V_), MAX_V_);
                out_b[(size_t)(eb + e) * (FS_*T_) + (T_ - 1)] = xv;
            }
        }
    }
}

extern "C" void kernel_launch(void* const* d_in, const int* in_sizes, int n_in,
                              void* d_out, int out_size) {
    (void)in_sizes; (void)n_in; (void)out_size;
    // metadata order: ts, in_signal, x0, noise, Wf1, bf1, Wf2, bf2, Wg1, bg1, Wg2, bg2
    const float* a_in  = (const float*)d_in[1];
    const float* x0    = (const float*)d_in[2];
    const float* noise = (const float*)d_in[3];
    const float* Wf1   = (const float*)d_in[4];
    const float* bf1   = (const float*)d_in[5];
    const float* Wf2   = (const float*)d_in[6];
    const float* bf2   = (const float*)d_in[7];
    const float* Wg1   = (const float*)d_in[8];
    const float* bg1   = (const float*)d_in[9];
    const float* Wg2   = (const float*)d_in[10];
    const float* bg2   = (const float*)d_in[11];
    float* out = (float*)d_out;

    sde_kernel<<<B_ / 16, 128>>>(a_in, x0, noise,
                                 Wf1, bf1, Wf2, bf2,
                                 Wg1, bg1, Wg2, bg2,
                                 out);
}